// round 5
// baseline (speedup 1.0000x reference)
#include <cuda_runtime.h>
#include <cuda_bf16.h>
#include <cstdint>
#include <cstddef>

// ---------------------------------------------------------------------------
// QuantizedLinear: out[M,N] = x[M,K] @ (wq*scale)[N,K]^T + bias
// M = 16384, K = 4096, N = 16384, fp32 I/O.
// Build target is virtual compute_103 (no 'a') -> tcgen05 unavailable.
// Path: mma.sync.m16n8k16 bf16 (HMMA) + cp.async + ldmatrix.
// Numerics: W exact in bf16 (ints 0..126), x split hi+lo bf16, two MMA
// passes into fp32 register accumulators, scale/bias in fp32 epilogue.
// ---------------------------------------------------------------------------

#define MTOT 16384
#define NTOT 16384
#define KTOT 4096

#define BM 128
#define BN 128
#define BK 64
#define NKSTEP (KTOT / BK)   // 64
#define STAGES 4

// SMEM layout
#define SM_SCALE 0           // 128 f32
#define SM_BIAS  512         // 128 f32
#define SM_BUF   1024
#define AHI_OFF  0           // 128 rows x 128B
#define ALO_OFF  16384
#define BW_OFF   32768
#define STAGE_BYTES 49152
#define SMEM_TOTAL (SM_BUF + STAGES * STAGE_BYTES)   // 197632

// -------------------- scratch ----------------------------------------------
__device__ __nv_bfloat16 g_xhi[(size_t)MTOT * KTOT];
__device__ __nv_bfloat16 g_xlo[(size_t)MTOT * KTOT];
__device__ __nv_bfloat16 g_w  [(size_t)NTOT * KTOT];

// -------------------- PTX helpers ------------------------------------------
__device__ __forceinline__ uint32_t smem_u32(const void* p) {
    uint32_t a;
    asm("{ .reg .u64 t; cvta.to.shared.u64 t, %1; cvt.u32.u64 %0, t; }" : "=r"(a) : "l"(p));
    return a;
}
#define CP_ASYNC16(dst, src) \
    asm volatile("cp.async.cg.shared.global [%0], [%1], 16;" :: "r"(dst), "l"(src) : "memory")
#define CP_COMMIT() asm volatile("cp.async.commit_group;" ::: "memory")
#define CP_WAIT(n)  asm volatile("cp.async.wait_group %0;" :: "n"(n) : "memory")

__device__ __forceinline__ void ldsm_x4(uint32_t& r0, uint32_t& r1, uint32_t& r2, uint32_t& r3,
                                        uint32_t a) {
    asm volatile("ldmatrix.sync.aligned.m8n8.x4.shared.b16 {%0,%1,%2,%3}, [%4];"
                 : "=r"(r0), "=r"(r1), "=r"(r2), "=r"(r3) : "r"(a));
}
__device__ __forceinline__ void ldsm_x2(uint32_t& r0, uint32_t& r1, uint32_t a) {
    asm volatile("ldmatrix.sync.aligned.m8n8.x2.shared.b16 {%0,%1}, [%2];"
                 : "=r"(r0), "=r"(r1) : "r"(a));
}
__device__ __forceinline__ void mma_bf16(float* d, const uint32_t* a, const uint32_t* b) {
    asm volatile("mma.sync.aligned.m16n8k16.row.col.f32.bf16.bf16.f32 "
                 "{%0,%1,%2,%3}, {%4,%5,%6,%7}, {%8,%9}, {%0,%1,%2,%3};"
                 : "+f"(d[0]), "+f"(d[1]), "+f"(d[2]), "+f"(d[3])
                 : "r"(a[0]), "r"(a[1]), "r"(a[2]), "r"(a[3]), "r"(b[0]), "r"(b[1]));
}
__device__ __forceinline__ uint32_t sw128(uint32_t o) { return o ^ ((o >> 3) & 0x70); }

// -------------------- prep kernels -----------------------------------------
__global__ void prep_w_kernel(const int* __restrict__ wq) {
    size_t i = (size_t)blockIdx.x * blockDim.x + threadIdx.x;  // 4 elems each
    int4 v = reinterpret_cast<const int4*>(wq)[i];
    union { __nv_bfloat16 h[4]; uint2 u; } r;
    r.h[0] = __float2bfloat16_rn((float)v.x);
    r.h[1] = __float2bfloat16_rn((float)v.y);
    r.h[2] = __float2bfloat16_rn((float)v.z);
    r.h[3] = __float2bfloat16_rn((float)v.w);
    reinterpret_cast<uint2*>(g_w)[i] = r.u;
}

__global__ void prep_x_kernel(const float* __restrict__ x) {
    size_t i = (size_t)blockIdx.x * blockDim.x + threadIdx.x;  // 4 elems each
    float4 v = reinterpret_cast<const float4*>(x)[i];
    union { __nv_bfloat16 h[4]; uint2 u; } hi, lo;
    float f[4] = {v.x, v.y, v.z, v.w};
#pragma unroll
    for (int j = 0; j < 4; j++) {
        __nv_bfloat16 h = __float2bfloat16_rn(f[j]);
        hi.h[j] = h;
        lo.h[j] = __float2bfloat16_rn(f[j] - __bfloat162float(h));
    }
    reinterpret_cast<uint2*>(g_xhi)[i] = hi.u;
    reinterpret_cast<uint2*>(g_xlo)[i] = lo.u;
}

// -------------------- GEMM kernel ------------------------------------------
__global__ __launch_bounds__(256, 1)
void gemm_kernel(const float* __restrict__ scale, const float* __restrict__ bias,
                 float* __restrict__ out) {
    extern __shared__ __align__(1024) char smem[];
    const uint32_t sb = smem_u32(smem);
    const int tid  = threadIdx.x;
    const int wid  = tid >> 5;
    const int lane = tid & 31;

    // rasterize: groups of 8 M-tiles sweep all 128 N-tiles (L2 reuse of B)
    const int bid = blockIdx.x;
    const int grp = bid >> 10;
    const int r   = bid & 1023;
    const int mt  = (grp << 3) + (r & 7);
    const int nt  = r >> 3;

    // global tile bases
    const char* pahi = (const char*)g_xhi + (size_t)mt * BM * (KTOT * 2);
    const char* palo = (const char*)g_xlo + (size_t)mt * BM * (KTOT * 2);
    const char* pbw  = (const char*)g_w   + (size_t)nt * BN * (KTOT * 2);

    // per-thread cp.async addressing: seg = 16B segment, rows r0+32j
    const int seg = tid & 7;
    const int rb  = tid >> 3;
    uint32_t smoff[4];
    size_t   goff[4];
#pragma unroll
    for (int j = 0; j < 4; j++) {
        int row = rb + 32 * j;
        smoff[j] = sw128((uint32_t)(row * 128 + seg * 16));
        goff[j]  = (size_t)row * (KTOT * 2) + seg * 16;
    }

    // load scale/bias early
    float* s_scale = reinterpret_cast<float*>(smem + SM_SCALE);
    float* s_bias  = reinterpret_cast<float*>(smem + SM_BIAS);
    if (tid < 128) {
        s_scale[tid] = scale[nt * BN + tid];
        s_bias[tid]  = bias[nt * BN + tid];
    }

    // prologue: stages 0..2
#pragma unroll
    for (int s = 0; s < STAGES - 1; s++) {
        const uint32_t sa = sb + SM_BUF + s * STAGE_BYTES;
        const size_t kofs = (size_t)s * (BK * 2);
#pragma unroll
        for (int j = 0; j < 4; j++) {
            CP_ASYNC16(sa + AHI_OFF + smoff[j], pahi + goff[j] + kofs);
            CP_ASYNC16(sa + ALO_OFF + smoff[j], palo + goff[j] + kofs);
            CP_ASYNC16(sa + BW_OFF  + smoff[j], pbw  + goff[j] + kofs);
        }
        CP_COMMIT();
    }

    // warp tiling: 2 (M) x 4 (N); warp tile 64x32
    const int m_off = (wid >> 2) * 64;
    const int n_off = (wid & 3) * 32;

    // ldmatrix per-lane row/col selectors
    const int aRow  = lane & 15;           // m row within 16
    const int aCol8 = ((lane >> 4) & 1) * 8;   // k half
    const int bRow  = lane & 7;            // n row within 8
    const int bCol8 = ((lane >> 3) & 1) * 8;   // k half

    float acc[4][4][4];
#pragma unroll
    for (int im = 0; im < 4; im++)
#pragma unroll
        for (int jn = 0; jn < 4; jn++)
#pragma unroll
            for (int q = 0; q < 4; q++) acc[im][jn][q] = 0.0f;

#pragma unroll 1
    for (int ks = 0; ks < NKSTEP; ks++) {
        CP_WAIT(2);              // stage ks resident
        __syncthreads();         // all warps done with stage (ks-1)%4

        // issue load for stage ks+3 (overwrites stage (ks-1)%4)
        if (ks + STAGES - 1 < NKSTEP) {
            const uint32_t sa = sb + SM_BUF + ((ks + STAGES - 1) & 3) * STAGE_BYTES;
            const size_t kofs = (size_t)(ks + STAGES - 1) * (BK * 2);
#pragma unroll
            for (int j = 0; j < 4; j++) {
                CP_ASYNC16(sa + AHI_OFF + smoff[j], pahi + goff[j] + kofs);
                CP_ASYNC16(sa + ALO_OFF + smoff[j], palo + goff[j] + kofs);
                CP_ASYNC16(sa + BW_OFF  + smoff[j], pbw  + goff[j] + kofs);
            }
        }
        CP_COMMIT();             // commit every iter (empty groups keep count aligned)

        const uint32_t sa = sb + SM_BUF + (ks & 3) * STAGE_BYTES;
#pragma unroll
        for (int kk = 0; kk < 4; kk++) {           // 4 k-steps of 16 within BK=64
            const int colA = kk * 32 + aCol8 * 2;  // byte col within 128B row
            const int colB = kk * 32 + bCol8 * 2;

            uint32_t ah[4][4], al[4][4], bf[4][2];
#pragma unroll
            for (int im = 0; im < 4; im++) {
                int row = m_off + im * 16 + aRow;
                uint32_t off = sw128((uint32_t)(row * 128 + colA));
                ldsm_x4(ah[im][0], ah[im][1], ah[im][2], ah[im][3], sa + AHI_OFF + off);
                ldsm_x4(al[im][0], al[im][1], al[im][2], al[im][3], sa + ALO_OFF + off);
            }
#pragma unroll
            for (int jn = 0; jn < 4; jn++) {
                int row = n_off + jn * 8 + bRow;
                uint32_t off = sw128((uint32_t)(row * 128 + colB));
                ldsm_x2(bf[jn][0], bf[jn][1], sa + BW_OFF + off);
            }
#pragma unroll
            for (int im = 0; im < 4; im++)
#pragma unroll
                for (int jn = 0; jn < 4; jn++)
                    mma_bf16(acc[im][jn], ah[im], bf[jn]);
#pragma unroll
            for (int im = 0; im < 4; im++)
#pragma unroll
                for (int jn = 0; jn < 4; jn++)
                    mma_bf16(acc[im][jn], al[im], bf[jn]);
        }
    }
    CP_WAIT(0);
    __syncthreads();

    // ---------------- epilogue: scale/bias + store (float2) ----------------
    const int dRow = lane >> 2;          // 0..7
    const int dCol = (lane & 3) * 2;     // 0,2,4,6
    const size_t obase = (size_t)(mt * BM) * NTOT + (size_t)nt * BN;

#pragma unroll
    for (int im = 0; im < 4; im++) {
#pragma unroll
        for (int jn = 0; jn < 4; jn++) {
            const int c  = n_off + jn * 8 + dCol;
            const float s0 = s_scale[c],     b0 = s_bias[c];
            const float s1 = s_scale[c + 1], b1 = s_bias[c + 1];
            const int r0 = m_off + im * 16 + dRow;
            float2 v0 = make_float2(acc[im][jn][0] * s0 + b0, acc[im][jn][1] * s1 + b1);
            float2 v1 = make_float2(acc[im][jn][2] * s0 + b0, acc[im][jn][3] * s1 + b1);
            *reinterpret_cast<float2*>(out + obase + (size_t)r0 * NTOT + c)       = v0;
            *reinterpret_cast<float2*>(out + obase + (size_t)(r0 + 8) * NTOT + c) = v1;
        }
    }
}

// -------------------- launch ------------------------------------------------
extern "C" void kernel_launch(void* const* d_in, const int* in_sizes, int n_in,
                              void* d_out, int out_size) {
    (void)in_sizes; (void)n_in; (void)out_size;
    const float* x    = (const float*)d_in[0];
    const int*   wq   = (const int*)d_in[1];
    const float* wsc  = (const float*)d_in[2];
    const float* bias = (const float*)d_in[3];
    float*       out  = (float*)d_out;

    cudaFuncSetAttribute(gemm_kernel, cudaFuncAttributeMaxDynamicSharedMemorySize, SMEM_TOTAL);

    prep_w_kernel<<<65536, 256>>>(wq);
    prep_x_kernel<<<65536, 256>>>(x);

    // (16384/128)^2 = 16384 tiles
    gemm_kernel<<<16384, 256, SMEM_TOTAL>>>(wsc, bias, out);
}

// round 10
// speedup vs baseline: 1.8722x; 1.8722x over previous
#include <cuda_runtime.h>
#include <cuda_fp16.h>
#include <cstdint>
#include <cstddef>

// ---------------------------------------------------------------------------
// QuantizedLinear: out[M,N] = x[M,K] @ (wq*scale)[N,K]^T + bias
// M = 16384, K = 4096, N = 16384, fp32 I/O.  Target: SIMT mma.sync (HMMA),
// since the harness lowers PTX at compute_103 (no 'a') -> no tcgen05.
// Numerics: single-pass fp16. wq in [0,127) exact in fp16; fp16xfp16 products
// exact in fp32 accum; only x-rounding contributes error (~2e-4 << 1e-3).
// 2 CTAs/SM (3-stage 97KB pipeline) to hide sync/LDSM latency under HMMA.
// ---------------------------------------------------------------------------

#define MTOT 16384
#define NTOT 16384
#define KTOT 4096

#define BM 128
#define BN 128
#define BK 64
#define NKSTEP (KTOT / BK)   // 64
#define STAGES 3

// SMEM layout
#define SM_SCALE 0           // 128 f32
#define SM_BIAS  512         // 128 f32
#define SM_BUF   1024
#define A_OFF    0           // 128 rows x 128B (fp16, BK=64)
#define B_OFF    16384
#define STAGE_BYTES 32768
#define SMEM_TOTAL (SM_BUF + STAGES * STAGE_BYTES)   // 99328 -> 2 CTAs/SM

// -------------------- scratch ----------------------------------------------
__device__ __half g_xh[(size_t)MTOT * KTOT];
__device__ __half g_w [(size_t)NTOT * KTOT];

// -------------------- PTX helpers ------------------------------------------
__device__ __forceinline__ uint32_t smem_u32(const void* p) {
    uint32_t a;
    asm("{ .reg .u64 t; cvta.to.shared.u64 t, %1; cvt.u32.u64 %0, t; }" : "=r"(a) : "l"(p));
    return a;
}
#define CP_ASYNC16(dst, src) \
    asm volatile("cp.async.cg.shared.global [%0], [%1], 16;" :: "r"(dst), "l"(src) : "memory")
#define CP_COMMIT() asm volatile("cp.async.commit_group;" ::: "memory")
#define CP_WAIT(n)  asm volatile("cp.async.wait_group %0;" :: "n"(n) : "memory")

__device__ __forceinline__ void ldsm_x4(uint32_t& r0, uint32_t& r1, uint32_t& r2, uint32_t& r3,
                                        uint32_t a) {
    asm volatile("ldmatrix.sync.aligned.m8n8.x4.shared.b16 {%0,%1,%2,%3}, [%4];"
                 : "=r"(r0), "=r"(r1), "=r"(r2), "=r"(r3) : "r"(a));
}
__device__ __forceinline__ void ldsm_x2(uint32_t& r0, uint32_t& r1, uint32_t a) {
    asm volatile("ldmatrix.sync.aligned.m8n8.x2.shared.b16 {%0,%1}, [%2];"
                 : "=r"(r0), "=r"(r1) : "r"(a));
}
__device__ __forceinline__ void mma_f16(float* d, const uint32_t* a, const uint32_t* b) {
    asm volatile("mma.sync.aligned.m16n8k16.row.col.f32.f16.f16.f32 "
                 "{%0,%1,%2,%3}, {%4,%5,%6,%7}, {%8,%9}, {%0,%1,%2,%3};"
                 : "+f"(d[0]), "+f"(d[1]), "+f"(d[2]), "+f"(d[3])
                 : "r"(a[0]), "r"(a[1]), "r"(a[2]), "r"(a[3]), "r"(b[0]), "r"(b[1]));
}
__device__ __forceinline__ uint32_t sw128(uint32_t o) { return o ^ ((o >> 3) & 0x70); }

// -------------------- prep kernels -----------------------------------------
__global__ void prep_w_kernel(const int* __restrict__ wq) {
    size_t i = (size_t)blockIdx.x * blockDim.x + threadIdx.x;  // 4 elems each
    int4 v = reinterpret_cast<const int4*>(wq)[i];
    union { __half h[4]; uint2 u; } r;
    r.h[0] = __int2half_rn(v.x);
    r.h[1] = __int2half_rn(v.y);
    r.h[2] = __int2half_rn(v.z);
    r.h[3] = __int2half_rn(v.w);
    reinterpret_cast<uint2*>(g_w)[i] = r.u;
}

__global__ void prep_x_kernel(const float* __restrict__ x) {
    size_t i = (size_t)blockIdx.x * blockDim.x + threadIdx.x;  // 4 elems each
    float4 v = reinterpret_cast<const float4*>(x)[i];
    union { __half h[4]; uint2 u; } r;
    r.h[0] = __float2half_rn(v.x);
    r.h[1] = __float2half_rn(v.y);
    r.h[2] = __float2half_rn(v.z);
    r.h[3] = __float2half_rn(v.w);
    reinterpret_cast<uint2*>(g_xh)[i] = r.u;
}

// -------------------- GEMM kernel ------------------------------------------
__global__ __launch_bounds__(256, 2)
void gemm_kernel(const float* __restrict__ scale, const float* __restrict__ bias,
                 float* __restrict__ out) {
    extern __shared__ __align__(1024) char smem[];
    const uint32_t sb = smem_u32(smem);
    const int tid  = threadIdx.x;
    const int wid  = tid >> 5;
    const int lane = tid & 31;

    // rasterize: groups of 8 M-tiles sweep all 128 N-tiles (L2 reuse of B)
    const int bid = blockIdx.x;
    const int grp = bid >> 10;
    const int r   = bid & 1023;
    const int mt  = (grp << 3) + (r & 7);
    const int nt  = r >> 3;

    const char* pa = (const char*)g_xh + (size_t)mt * BM * (KTOT * 2);
    const char* pb = (const char*)g_w  + (size_t)nt * BN * (KTOT * 2);

    // per-thread cp.async addressing: seg = 16B segment, rows rb+32j
    const int seg = tid & 7;
    const int rb  = tid >> 3;
    uint32_t smoff[4];
    size_t   goff[4];
#pragma unroll
    for (int j = 0; j < 4; j++) {
        int row = rb + 32 * j;
        smoff[j] = sw128((uint32_t)(row * 128 + seg * 16));
        goff[j]  = (size_t)row * (KTOT * 2) + seg * 16;
    }

    float* s_scale = reinterpret_cast<float*>(smem + SM_SCALE);
    float* s_bias  = reinterpret_cast<float*>(smem + SM_BIAS);
    if (tid < 128) {
        s_scale[tid] = scale[nt * BN + tid];
        s_bias[tid]  = bias[nt * BN + tid];
    }

    // prologue: stages 0..1
#pragma unroll
    for (int s = 0; s < STAGES - 1; s++) {
        const uint32_t sa = sb + SM_BUF + s * STAGE_BYTES;
        const size_t kofs = (size_t)s * (BK * 2);
#pragma unroll
        for (int j = 0; j < 4; j++) {
            CP_ASYNC16(sa + A_OFF + smoff[j], pa + goff[j] + kofs);
            CP_ASYNC16(sa + B_OFF + smoff[j], pb + goff[j] + kofs);
        }
        CP_COMMIT();
    }

    // warp tiling: 2 (M) x 4 (N); warp tile 64x32
    const int m_off = (wid >> 2) * 64;
    const int n_off = (wid & 3) * 32;

    const int aRow  = lane & 15;
    const int aCol8 = ((lane >> 4) & 1) * 8;
    const int bRow  = lane & 7;
    const int bCol8 = ((lane >> 3) & 1) * 8;

    float acc[4][4][4];
#pragma unroll
    for (int im = 0; im < 4; im++)
#pragma unroll
        for (int jn = 0; jn < 4; jn++)
#pragma unroll
            for (int q = 0; q < 4; q++) acc[im][jn][q] = 0.0f;

#pragma unroll 1
    for (int ks = 0; ks < NKSTEP; ks++) {
        CP_WAIT(1);              // stage ks resident (1 group may remain in flight)
        __syncthreads();         // all warps done with stage (ks-1)%3

        // issue load for stage ks+2 (overwrites stage (ks-1)%3)
        if (ks + STAGES - 1 < NKSTEP) {
            const uint32_t sa = sb + SM_BUF + ((ks + STAGES - 1) % STAGES) * STAGE_BYTES;
            const size_t kofs = (size_t)(ks + STAGES - 1) * (BK * 2);
#pragma unroll
            for (int j = 0; j < 4; j++) {
                CP_ASYNC16(sa + A_OFF + smoff[j], pa + goff[j] + kofs);
                CP_ASYNC16(sa + B_OFF + smoff[j], pb + goff[j] + kofs);
            }
        }
        CP_COMMIT();             // commit every iter to keep group count aligned

        const uint32_t sa = sb + SM_BUF + (ks % STAGES) * STAGE_BYTES;
#pragma unroll
        for (int kk = 0; kk < 4; kk++) {           // 4 k-steps of 16 within BK=64
            const int colA = kk * 32 + aCol8 * 2;
            const int colB = kk * 32 + bCol8 * 2;

            uint32_t af[4][4], bf[4][2];
#pragma unroll
            for (int im = 0; im < 4; im++) {
                int row = m_off + im * 16 + aRow;
                uint32_t off = sw128((uint32_t)(row * 128 + colA));
                ldsm_x4(af[im][0], af[im][1], af[im][2], af[im][3], sa + A_OFF + off);
            }
#pragma unroll
            for (int jn = 0; jn < 4; jn++) {
                int row = n_off + jn * 8 + bRow;
                uint32_t off = sw128((uint32_t)(row * 128 + colB));
                ldsm_x2(bf[jn][0], bf[jn][1], sa + B_OFF + off);
            }
#pragma unroll
            for (int im = 0; im < 4; im++)
#pragma unroll
                for (int jn = 0; jn < 4; jn++)
                    mma_f16(acc[im][jn], af[im], bf[jn]);
        }
    }
    CP_WAIT(0);
    __syncthreads();

    // ---------------- epilogue: scale/bias + store (float2) ----------------
    const int dRow = lane >> 2;          // 0..7
    const int dCol = (lane & 3) * 2;     // 0,2,4,6
    const size_t obase = (size_t)(mt * BM) * NTOT + (size_t)nt * BN;

#pragma unroll
    for (int im = 0; im < 4; im++) {
#pragma unroll
        for (int jn = 0; jn < 4; jn++) {
            const int c  = n_off + jn * 8 + dCol;
            const float s0 = s_scale[c],     b0 = s_bias[c];
            const float s1 = s_scale[c + 1], b1 = s_bias[c + 1];
            const int r0 = m_off + im * 16 + dRow;
            float2 v0 = make_float2(acc[im][jn][0] * s0 + b0, acc[im][jn][1] * s1 + b1);
            float2 v1 = make_float2(acc[im][jn][2] * s0 + b0, acc[im][jn][3] * s1 + b1);
            *reinterpret_cast<float2*>(out + obase + (size_t)r0 * NTOT + c)       = v0;
            *reinterpret_cast<float2*>(out + obase + (size_t)(r0 + 8) * NTOT + c) = v1;
        }
    }
}

// -------------------- launch ------------------------------------------------
extern "C" void kernel_launch(void* const* d_in, const int* in_sizes, int n_in,
                              void* d_out, int out_size) {
    (void)in_sizes; (void)n_in; (void)out_size;
    const float* x    = (const float*)d_in[0];
    const int*   wq   = (const int*)d_in[1];
    const float* wsc  = (const float*)d_in[2];
    const float* bias = (const float*)d_in[3];
    float*       out  = (float*)d_out;

    cudaFuncSetAttribute(gemm_kernel, cudaFuncAttributeMaxDynamicSharedMemorySize, SMEM_TOTAL);

    prep_w_kernel<<<65536, 256>>>(wq);
    prep_x_kernel<<<65536, 256>>>(x);

    // (16384/128)^2 = 16384 tiles
    gemm_kernel<<<16384, 256, SMEM_TOTAL>>>(wsc, bias, out);
}

// round 13
// speedup vs baseline: 2.0283x; 1.0834x over previous
#include <cuda_runtime.h>
#include <cuda_fp16.h>
#include <cstdint>
#include <cstddef>

// ---------------------------------------------------------------------------
// QuantizedLinear: out[M,N] = x[M,K] @ (wq*scale)[N,K]^T + bias
// M = 16384, K = 4096, N = 16384, fp32 I/O.  SIMT mma.sync (HMMA) path
// (harness lowers PTX at compute_103 -> no tcgen05).
// Numerics: single-pass fp16 (validated: rel_err 2.09e-4 < 1e-3).
// R11 change: warp tile 64x32 -> 64x64 (4 warps/CTA, 128 thr) to cut SMEM
// crossbar fragment traffic 33% (0.092 -> 0.061 B/MAC); B via ldmatrix.x4.
// ---------------------------------------------------------------------------

#define MTOT 16384
#define NTOT 16384
#define KTOT 4096

#define BM 128
#define BN 128
#define BK 64
#define NKSTEP (KTOT / BK)   // 64
#define STAGES 3
#define THREADS 128

// SMEM layout
#define SM_SCALE 0           // 128 f32
#define SM_BIAS  512         // 128 f32
#define SM_BUF   1024
#define A_OFF    0           // 128 rows x 128B (fp16, BK=64)
#define B_OFF    16384
#define STAGE_BYTES 32768
#define SMEM_TOTAL (SM_BUF + STAGES * STAGE_BYTES)   // 99328 -> 2 CTAs/SM

// -------------------- scratch ----------------------------------------------
__device__ __half g_xh[(size_t)MTOT * KTOT];
__device__ __half g_w [(size_t)NTOT * KTOT];

// -------------------- PTX helpers ------------------------------------------
__device__ __forceinline__ uint32_t smem_u32(const void* p) {
    uint32_t a;
    asm("{ .reg .u64 t; cvta.to.shared.u64 t, %1; cvt.u32.u64 %0, t; }" : "=r"(a) : "l"(p));
    return a;
}
#define CP_ASYNC16(dst, src) \
    asm volatile("cp.async.cg.shared.global [%0], [%1], 16;" :: "r"(dst), "l"(src) : "memory")
#define CP_COMMIT() asm volatile("cp.async.commit_group;" ::: "memory")
#define CP_WAIT(n)  asm volatile("cp.async.wait_group %0;" :: "n"(n) : "memory")

__device__ __forceinline__ void ldsm_x4(uint32_t& r0, uint32_t& r1, uint32_t& r2, uint32_t& r3,
                                        uint32_t a) {
    asm volatile("ldmatrix.sync.aligned.m8n8.x4.shared.b16 {%0,%1,%2,%3}, [%4];"
                 : "=r"(r0), "=r"(r1), "=r"(r2), "=r"(r3) : "r"(a));
}
__device__ __forceinline__ void mma_f16(float* d, const uint32_t* a, const uint32_t* b) {
    asm volatile("mma.sync.aligned.m16n8k16.row.col.f32.f16.f16.f32 "
                 "{%0,%1,%2,%3}, {%4,%5,%6,%7}, {%8,%9}, {%0,%1,%2,%3};"
                 : "+f"(d[0]), "+f"(d[1]), "+f"(d[2]), "+f"(d[3])
                 : "r"(a[0]), "r"(a[1]), "r"(a[2]), "r"(a[3]), "r"(b[0]), "r"(b[1]));
}
__device__ __forceinline__ uint32_t sw128(uint32_t o) { return o ^ ((o >> 3) & 0x70); }

// -------------------- prep kernels -----------------------------------------
__global__ void prep_w_kernel(const int* __restrict__ wq) {
    size_t i = (size_t)blockIdx.x * blockDim.x + threadIdx.x;  // 4 elems each
    int4 v = reinterpret_cast<const int4*>(wq)[i];
    union { __half h[4]; uint2 u; } r;
    r.h[0] = __int2half_rn(v.x);
    r.h[1] = __int2half_rn(v.y);
    r.h[2] = __int2half_rn(v.z);
    r.h[3] = __int2half_rn(v.w);
    reinterpret_cast<uint2*>(g_w)[i] = r.u;
}

__global__ void prep_x_kernel(const float* __restrict__ x) {
    size_t i = (size_t)blockIdx.x * blockDim.x + threadIdx.x;  // 4 elems each
    float4 v = reinterpret_cast<const float4*>(x)[i];
    union { __half h[4]; uint2 u; } r;
    r.h[0] = __float2half_rn(v.x);
    r.h[1] = __float2half_rn(v.y);
    r.h[2] = __float2half_rn(v.z);
    r.h[3] = __float2half_rn(v.w);
    reinterpret_cast<uint2*>(g_xh)[i] = r.u;
}

// -------------------- GEMM kernel ------------------------------------------
__global__ __launch_bounds__(THREADS, 2)
void gemm_kernel(const float* __restrict__ scale, const float* __restrict__ bias,
                 float* __restrict__ out) {
    extern __shared__ __align__(1024) char smem[];
    const uint32_t sb = smem_u32(smem);
    const int tid  = threadIdx.x;
    const int wid  = tid >> 5;
    const int lane = tid & 31;

    // rasterize: groups of 8 M-tiles sweep all 128 N-tiles (L2 reuse of B)
    const int bid = blockIdx.x;
    const int grp = bid >> 10;
    const int r   = bid & 1023;
    const int mt  = (grp << 3) + (r & 7);
    const int nt  = r >> 3;

    const char* pa = (const char*)g_xh + (size_t)mt * BM * (KTOT * 2);
    const char* pb = (const char*)g_w  + (size_t)nt * BN * (KTOT * 2);

    // per-thread cp.async addressing: 128 threads, seg = 16B segment,
    // rows rb+16j (j=0..7) -> 8 A + 8 B cp.async per thread per stage
    const int seg = tid & 7;
    const int rb  = tid >> 3;      // 0..15
    uint32_t smoff[8];
    size_t   goff[8];
#pragma unroll
    for (int j = 0; j < 8; j++) {
        int row = rb + 16 * j;
        smoff[j] = sw128((uint32_t)(row * 128 + seg * 16));
        goff[j]  = (size_t)row * (KTOT * 2) + seg * 16;
    }

    float* s_scale = reinterpret_cast<float*>(smem + SM_SCALE);
    float* s_bias  = reinterpret_cast<float*>(smem + SM_BIAS);
    s_scale[tid] = scale[nt * BN + tid];
    s_bias[tid]  = bias[nt * BN + tid];

    // prologue: stages 0..1
#pragma unroll
    for (int s = 0; s < STAGES - 1; s++) {
        const uint32_t sa = sb + SM_BUF + s * STAGE_BYTES;
        const size_t kofs = (size_t)s * (BK * 2);
#pragma unroll
        for (int j = 0; j < 8; j++) {
            CP_ASYNC16(sa + A_OFF + smoff[j], pa + goff[j] + kofs);
            CP_ASYNC16(sa + B_OFF + smoff[j], pb + goff[j] + kofs);
        }
        CP_COMMIT();
    }

    // warp tiling: 2 (M) x 2 (N); warp tile 64x64
    const int m_off = (wid >> 1) * 64;
    const int n_off = (wid & 1) * 64;

    // A ldmatrix.x4 lane selectors (m16 x k16 fragment)
    const int aRow  = lane & 15;
    const int aCol8 = ((lane >> 4) & 1) * 8;       // k half
    // B ldmatrix.x4 lane selectors: pieces {n8 lo-k, n8 hi-k, (n+8) lo-k, (n+8) hi-k}
    const int bRow  = (lane & 7) + ((lane >> 4) & 1) * 8;  // row within 16-row pair
    const int bCol  = ((lane >> 3) & 1) * 16;              // k-half byte offset

    float acc[4][8][4];
#pragma unroll
    for (int im = 0; im < 4; im++)
#pragma unroll
        for (int jn = 0; jn < 8; jn++)
#pragma unroll
            for (int q = 0; q < 4; q++) acc[im][jn][q] = 0.0f;

#pragma unroll 1
    for (int ks = 0; ks < NKSTEP; ks++) {
        CP_WAIT(1);              // stage ks resident (1 group may remain in flight)
        __syncthreads();         // all warps done with stage (ks-1)%3

        // issue load for stage ks+2 (overwrites stage (ks-1)%3)
        if (ks + STAGES - 1 < NKSTEP) {
            const uint32_t sa = sb + SM_BUF + ((ks + STAGES - 1) % STAGES) * STAGE_BYTES;
            const size_t kofs = (size_t)(ks + STAGES - 1) * (BK * 2);
#pragma unroll
            for (int j = 0; j < 8; j++) {
                CP_ASYNC16(sa + A_OFF + smoff[j], pa + goff[j] + kofs);
                CP_ASYNC16(sa + B_OFF + smoff[j], pb + goff[j] + kofs);
            }
        }
        CP_COMMIT();             // commit every iter to keep group count aligned

        const uint32_t sa = sb + SM_BUF + (ks % STAGES) * STAGE_BYTES;
#pragma unroll
        for (int kk = 0; kk < 4; kk++) {           // 4 k-steps of 16 within BK=64
            const int colA = kk * 32 + aCol8 * 2;
            const int colB = kk * 32 + bCol;

            uint32_t af[4][4], bf[8][2];
#pragma unroll
            for (int im = 0; im < 4; im++) {
                int row = m_off + im * 16 + aRow;
                uint32_t off = sw128((uint32_t)(row * 128 + colA));
                ldsm_x4(af[im][0], af[im][1], af[im][2], af[im][3], sa + A_OFF + off);
            }
#pragma unroll
            for (int jp = 0; jp < 4; jp++) {       // pairs of n8 tiles (16 rows)
                int row = n_off + jp * 16 + bRow;
                uint32_t off = sw128((uint32_t)(row * 128 + colB));
                ldsm_x4(bf[jp * 2][0], bf[jp * 2][1], bf[jp * 2 + 1][0], bf[jp * 2 + 1][1],
                        sa + B_OFF + off);
            }
#pragma unroll
            for (int im = 0; im < 4; im++)
#pragma unroll
                for (int jn = 0; jn < 8; jn++)
                    mma_f16(acc[im][jn], af[im], bf[jn]);
        }
    }
    CP_WAIT(0);
    __syncthreads();

    // ---------------- epilogue: scale/bias + store (float2) ----------------
    const int dRow = lane >> 2;          // 0..7
    const int dCol = (lane & 3) * 2;     // 0,2,4,6
    const size_t obase = (size_t)(mt * BM) * NTOT + (size_t)nt * BN;

#pragma unroll
    for (int im = 0; im < 4; im++) {
#pragma unroll
        for (int jn = 0; jn < 8; jn++) {
            const int c  = n_off + jn * 8 + dCol;
            const float s0 = s_scale[c],     b0 = s_bias[c];
            const float s1 = s_scale[c + 1], b1 = s_bias[c + 1];
            const int r0 = m_off + im * 16 + dRow;
            float2 v0 = make_float2(acc[im][jn][0] * s0 + b0, acc[im][jn][1] * s1 + b1);
            float2 v1 = make_float2(acc[im][jn][2] * s0 + b0, acc[im][jn][3] * s1 + b1);
            *reinterpret_cast<float2*>(out + obase + (size_t)r0 * NTOT + c)       = v0;
            *reinterpret_cast<float2*>(out + obase + (size_t)(r0 + 8) * NTOT + c) = v1;
        }
    }
}

// -------------------- launch ------------------------------------------------
extern "C" void kernel_launch(void* const* d_in, const int* in_sizes, int n_in,
                              void* d_out, int out_size) {
    (void)in_sizes; (void)n_in; (void)out_size;
    const float* x    = (const float*)d_in[0];
    const int*   wq   = (const int*)d_in[1];
    const float* wsc  = (const float*)d_in[2];
    const float* bias = (const float*)d_in[3];
    float*       out  = (float*)d_out;

    cudaFuncSetAttribute(gemm_kernel, cudaFuncAttributeMaxDynamicSharedMemorySize, SMEM_TOTAL);

    prep_w_kernel<<<65536, 256>>>(wq);
    prep_x_kernel<<<65536, 256>>>(x);

    // (16384/128)^2 = 16384 tiles
    gemm_kernel<<<16384, THREADS, SMEM_TOTAL>>>(wsc, bias, out);
}